// round 7
// baseline (speedup 1.0000x reference)
#include <cuda_runtime.h>
#include <cstdint>
#include <math.h>

#define HH 56
#define WW 56
#define NB 16
#define C1 64
#define C2 128
#define MU_C 0.1f
#define THR_C 0.01f

// ---------------- device scratch (allocation-free) ----------------
// fragment-ordered weights: [cib][tap][co_blk][kblk(4)][lane(32)][2]
__device__ float g_Wf[2 * 9 * (C2 / 8) * 4 * 64];
__device__ float g_Wt[4 * 9 * (C1 / 8) * 4 * 64];
__device__ float g_xn[NB * HH * WW * C1];   // x NHWC, full precision (residual aux)
__device__ float g_xr[NB * HH * WW * C1];   // x NHWC, tf32-rounded (conv input)
__device__ float g_y [NB * HH * WW * C2];   // y full precision (FISTA aux)
__device__ float g_yr[NB * HH * WW * C2];   // y tf32-rounded (tconv input)
__device__ float g_cp[NB * HH * WW * C2];   // c_prev full precision
__device__ float g_rr[NB * HH * WW * C1];   // residual, tf32-rounded (conv input)

__device__ __forceinline__ float rna_tf32(float v) {
    uint32_t o;
    asm("cvt.rna.tf32.f32 %0, %1;" : "=r"(o) : "f"(v));
    return __uint_as_float(o);
}

__device__ __forceinline__ void mma_tf32(float* d, const uint32_t* a, const uint32_t* b) {
    asm volatile(
        "mma.sync.aligned.m16n8k8.row.col.f32.tf32.tf32.f32 "
        "{%0,%1,%2,%3}, {%4,%5,%6,%7}, {%8,%9}, {%0,%1,%2,%3};"
        : "+f"(d[0]), "+f"(d[1]), "+f"(d[2]), "+f"(d[3])
        : "r"(a[0]), "r"(a[1]), "r"(a[2]), "r"(a[3]), "r"(b[0]), "r"(b[1]));
}

__device__ __forceinline__ uint32_t smem_u32(const void* p) {
    uint32_t a;
    asm("{ .reg .u64 t; cvta.to.shared.u64 t, %1; cvt.u32.u64 %0, t; }"
        : "=r"(a) : "l"(p));
    return a;
}
__device__ __forceinline__ void cp16(uint32_t dst, const void* src, int sz) {
    asm volatile("cp.async.cg.shared.global [%0], [%1], 16, %2;"
                 :: "r"(dst), "l"(src), "r"(sz));
}
__device__ __forceinline__ void cp_commit_wait() {
    asm volatile("cp.async.commit_group;");
    asm volatile("cp.async.wait_all;" ::: "memory");
}

// ---------------- prep kernels ----------------
__global__ void nchw2nhwc_kernel(const float* __restrict__ src,
                                 float* __restrict__ dfull, float* __restrict__ rnd) {
    int i = blockIdx.x * 256 + threadIdx.x;
    int total = NB * HH * WW * C1;
    if (i >= total) return;
    int c = i & 63;
    int p = i >> 6;
    int w = p % WW;
    int q = p / WW;
    int h = q % HH;
    int n = q / HH;
    float v = src[((n * C1 + c) * HH + h) * WW + w];
    dfull[i] = v;
    rnd[i] = rna_tf32(v);
}

__global__ void prep_w_kernel(const float* __restrict__ W) {
    const int co = blockIdx.x;
    const int tid = threadIdx.x;
    __shared__ float red[256];
    float s = 0.f;
    for (int i = tid; i < 576; i += 256) {
        float v = W[co * 576 + i];
        s += v * v;
    }
    red[tid] = s;
    __syncthreads();
    for (int off = 128; off > 0; off >>= 1) {
        if (tid < off) red[tid] += red[tid + off];
        __syncthreads();
    }
    const float inv = rsqrtf(red[0] + 1e-12f);
    for (int i = tid; i < 576; i += 256) {
        int ci = i / 9, tap = i - ci * 9;
        float v = rna_tf32(W[co * 576 + i] * inv);
        {   // forward: n = co, k = ci
            int lane = (co & 7) * 4 + (ci & 3);
            int reg  = (ci >> 2) & 1;
            int idx = (((((ci >> 5) * 9 + tap) * (C2 / 8) + (co >> 3)) * 4 +
                        ((ci & 31) >> 3)) * 32 + lane) * 2 + reg;
            g_Wf[idx] = v;
        }
        {   // transpose: n = ci, k = co, flipped tap
            int lane = (ci & 7) * 4 + (co & 3);
            int reg  = (co >> 2) & 1;
            int idx = (((((co >> 5) * 9 + (8 - tap)) * (C1 / 8) + (ci >> 3)) * 4 +
                        ((co & 31) >> 3)) * 32 + lane) * 2 + reg;
            g_Wt[idx] = v;
        }
    }
}

// ---------------- mma.sync implicit-GEMM conv, A-resident ----------------
// D[m=128 px (2 rows x 64 cols)][n=64 cout], K = 9 taps x CIN ci.
// A: 256 rows x CIN ci, resident in smem, XOR(row&7) 16B-unit swizzle.
// B: fwd (CIN=64) fully resident (both kh stages); tconv restaged per kh.
// MODE 0: first fwd;  MODE 1: FISTA fwd;  MODE 2: transpose conv + residual
template <int CIN, int COUT, int MODE>
__global__ __launch_bounds__(256)
void mconv(const float* __restrict__ in, const float* __restrict__ wgt,
           const float* __restrict__ aux0, const float* __restrict__ aux1,
           float* __restrict__ out0, float* __restrict__ out1,
           float* __restrict__ out2, float mcoef, int last)
{
    extern __shared__ char smem[];
    constexpr int STR  = CIN * 4;          // bytes per A row
    constexpr int UPR  = CIN / 4;          // 16B units per A row
    constexpr int KH   = CIN / 32;         // 32-ci k-super-stages
    constexpr bool BRES = (CIN == 64);     // all B resident?
    char* sAc = smem;
    float* sB = (float*)(smem + 256 * STR);
    const uint32_t sAu = smem_u32(smem);
    const uint32_t sBu = sAu + 256 * STR;

    const int tid  = threadIdx.x;
    const int lane = tid & 31;
    const int w    = tid >> 5;
    const int wm   = w & 3;
    const int wn   = w >> 2;
    const int g    = lane >> 2;
    const int t    = lane & 3;

    const int n   = blockIdx.z;
    const int h0  = blockIdx.y * 2;
    const int co0 = blockIdx.x * 64;
    const int cb0 = co0 >> 3;

    // ---- stage A (entire CIN), cp.async with zero-fill halo
    for (int i = tid; i < 256 * UPR; i += 256) {
        int row = i / UPR;
        int u   = i - row * UPR;
        int rr = row >> 6, cc = row & 63;
        int gh = h0 + rr - 1, gc = cc - 1;
        bool ok = ((unsigned)gh < (unsigned)HH) && ((unsigned)gc < (unsigned)WW);
        const float* src = in +
            (size_t)((n * HH + (ok ? gh : 0)) * WW + (ok ? gc : 0)) * CIN + u * 4;
        cp16(sAu + row * STR + (((uint32_t)(u ^ (row & 7))) << 4), src, ok ? 16 : 0);
    }
    // ---- stage B: fwd -> both stages now; tconv -> stage 0 now
    {
        const int nstage = BRES ? KH : 1;
        for (int kh = 0; kh < nstage; kh++) {
            for (int i = tid; i < 4608; i += 256) {
                int tap = i >> 9;
                int rem = i & 511;
                const float* src = wgt +
                    (size_t)((kh * 9 + tap) * (COUT / 8) + cb0) * 256 + rem * 4;
                cp16(sBu + kh * 73728 + tap * 8192 + rem * 16, src, 16);
            }
        }
    }
    cp_commit_wait();
    __syncthreads();

    float acc[2][4][4];
#pragma unroll
    for (int c = 0; c < 2; c++)
#pragma unroll
        for (int nb = 0; nb < 4; nb++)
#pragma unroll
            for (int j = 0; j < 4; j++) acc[c][nb][j] = 0.f;

    for (int kh = 0; kh < KH; kh++) {
        if (!BRES && kh > 0) {
            __syncthreads();                       // done reading previous B
            for (int i = tid; i < 4608; i += 256) {
                int tap = i >> 9;
                int rem = i & 511;
                const float* src = wgt +
                    (size_t)((kh * 9 + tap) * (COUT / 8) + cb0) * 256 + rem * 4;
                cp16(sBu + tap * 8192 + rem * 16, src, 16);
            }
            cp_commit_wait();
            __syncthreads();
        }
        const int bko = (BRES ? kh * 18432 : 0);   // float offset into sB

#pragma unroll 3
        for (int tap = 0; tap < 9; tap++) {
            const int tapoff = (tap / 3) * 64 + (tap % 3);
            const int mbA = wm * 32 + g + tapoff;          // c = 0 row
            const int mbB = mbA + 16;                      // c = 1 row
#pragma unroll
            for (int kblk = 0; kblk < 4; kblk++) {
                const int ub = kh * 8 + kblk * 2;          // 16B unit of k0
                uint32_t a[2][4];
#pragma unroll
                for (int c = 0; c < 2; c++) {
                    int mb0 = (c ? mbB : mbA);
                    int mb1 = mb0 + 8;
                    uint32_t p0 = mb0 * STR, p1 = mb1 * STR;
                    uint32_t x0 = (mb0 & 7) << 4, x1 = (mb1 & 7) << 4;
                    a[c][0] = *(const uint32_t*)(sAc + p0 + (((ub)     << 4) ^ x0) + t * 4);
                    a[c][1] = *(const uint32_t*)(sAc + p1 + (((ub)     << 4) ^ x1) + t * 4);
                    a[c][2] = *(const uint32_t*)(sAc + p0 + (((ub + 1) << 4) ^ x0) + t * 4);
                    a[c][3] = *(const uint32_t*)(sAc + p1 + (((ub + 1) << 4) ^ x1) + t * 4);
                }
#pragma unroll
                for (int nb = 0; nb < 4; nb++) {
                    float2 bv = *(const float2*)(sB + bko + tap * 2048 +
                                                 (wn * 4 + nb) * 256 + kblk * 64 + lane * 2);
                    uint32_t b[2];
                    b[0] = __float_as_uint(bv.x);
                    b[1] = __float_as_uint(bv.y);
                    mma_tf32(acc[0][nb], a[0], b);
                    mma_tf32(acc[1][nb], a[1], b);
                }
            }
        }
    }

    // ---- epilogue: fused FISTA ops
#pragma unroll
    for (int c = 0; c < 2; c++) {
#pragma unroll
        for (int half = 0; half < 2; half++) {
            int m = wm * 32 + c * 16 + g + half * 8;
            int rr = m >> 6, cc = m & 63;
            if (cc >= WW) continue;
            int h = h0 + rr;
            size_t pxb = (size_t)((n * HH + h) * WW + cc) * COUT + co0;
#pragma unroll
            for (int nb = 0; nb < 4; nb++) {
                int col = wn * 32 + nb * 8 + 2 * t;
                size_t o = pxb + col;
                float v0 = acc[c][nb][half * 2 + 0];
                float v1 = acc[c][nb][half * 2 + 1];
                if (MODE == 0) {
                    float2 r2;
                    r2.x = fmaxf(MU_C * v0 - THR_C, 0.f);
                    r2.y = fmaxf(MU_C * v1 - THR_C, 0.f);
                    *(float2*)(out0 + o) = r2;                       // y full
                    *(float2*)(out1 + o) = r2;                       // c_prev
                    float2 rr2; rr2.x = rna_tf32(r2.x); rr2.y = rna_tf32(r2.y);
                    *(float2*)(out2 + o) = rr2;                      // y rounded
                } else if (MODE == 1) {
                    float2 yv = *(const float2*)(aux0 + o);
                    float cn0 = fmaxf(yv.x + MU_C * v0 - THR_C, 0.f);
                    float cn1 = fmaxf(yv.y + MU_C * v1 - THR_C, 0.f);
                    if (last) {
                        out1[((size_t)(n * C2 + co0 + col) * HH + h) * WW + cc] = cn0;
                        out1[((size_t)(n * C2 + co0 + col + 1) * HH + h) * WW + cc] = cn1;
                    } else {
                        float2 cpv = *(const float2*)(aux1 + o);
                        float2 c2; c2.x = cn0; c2.y = cn1;
                        *(float2*)(out1 + o) = c2;                   // c_prev
                        float2 y2;
                        y2.x = cn0 + mcoef * (cn0 - cpv.x);
                        y2.y = cn1 + mcoef * (cn1 - cpv.y);
                        *(float2*)(out0 + o) = y2;                   // y full
                        float2 yr2; yr2.x = rna_tf32(y2.x); yr2.y = rna_tf32(y2.y);
                        *(float2*)(out2 + o) = yr2;                  // y rounded
                    }
                } else {
                    float2 xv = *(const float2*)(aux0 + o);
                    float2 r2;
                    r2.x = rna_tf32(xv.x - v0);
                    r2.y = rna_tf32(xv.y - v1);
                    *(float2*)(out0 + o) = r2;                       // r rounded
                }
            }
        }
    }
}

// ---------------- launcher ----------------
extern "C" void kernel_launch(void* const* d_in, const int* in_sizes, int n_in,
                              void* d_out, int out_size)
{
    const float* x = (const float*)d_in[0];   // [16,64,56,56] NCHW
    const float* W = (const float*)d_in[1];   // [128,64,3,3]
    float* out = (float*)d_out;               // [16,128,56,56] NCHW

    float *Wf, *Wt, *xn, *xr, *y, *yr, *cp, *rr;
    cudaGetSymbolAddress((void**)&Wf, g_Wf);
    cudaGetSymbolAddress((void**)&Wt, g_Wt);
    cudaGetSymbolAddress((void**)&xn, g_xn);
    cudaGetSymbolAddress((void**)&xr, g_xr);
    cudaGetSymbolAddress((void**)&y,  g_y);
    cudaGetSymbolAddress((void**)&yr, g_yr);
    cudaGetSymbolAddress((void**)&cp, g_cp);
    cudaGetSymbolAddress((void**)&rr, g_rr);

    float mv[5];
    {
        double t = 1.0;
        for (int i = 0; i < 5; i++) {
            double tn = (1.0 + sqrt(1.0 + 4.0 * t * t)) / 2.0;
            mv[i] = (float)((t - 1.0) / tn);
            t = tn;
        }
    }

    const int SMEM_F = 256 * (C1 * 4) + 2 * 73728;   // 212992 B (fwd)
    const int SMEM_T = 256 * (C2 * 4) + 73728;       // 204800 B (tconv)
    cudaFuncSetAttribute(mconv<C1, C2, 0>, cudaFuncAttributeMaxDynamicSharedMemorySize, SMEM_F);
    cudaFuncSetAttribute(mconv<C1, C2, 1>, cudaFuncAttributeMaxDynamicSharedMemorySize, SMEM_F);
    cudaFuncSetAttribute(mconv<C2, C1, 2>, cudaFuncAttributeMaxDynamicSharedMemorySize, SMEM_T);
    cudaFuncSetAttribute(mconv<C1, C2, 0>, cudaFuncAttributePreferredSharedMemoryCarveout, 100);
    cudaFuncSetAttribute(mconv<C1, C2, 1>, cudaFuncAttributePreferredSharedMemoryCarveout, 100);
    cudaFuncSetAttribute(mconv<C2, C1, 2>, cudaFuncAttributePreferredSharedMemoryCarveout, 100);

    int total = NB * HH * WW * C1;
    nchw2nhwc_kernel<<<(total + 255) / 256, 256>>>(x, xn, xr);
    prep_w_kernel<<<128, 256>>>(W);

    dim3 blk(256, 1, 1);
    dim3 grid_f(C2 / 64, HH / 2, NB);   // (2, 28, 16)
    dim3 grid_t(C1 / 64, HH / 2, NB);   // (1, 28, 16)

    // iteration 0: c = shrink(MU * D^T x); y = c; cp = c
    mconv<C1, C2, 0><<<grid_f, blk, SMEM_F>>>(xr, Wf, nullptr, nullptr, y, cp, yr, 0.f, 0);

    for (int it = 0; it < 5; it++) {
        // r = x - D y  (transpose conv + residual, rounded for next conv)
        mconv<C2, C1, 2><<<grid_t, blk, SMEM_T>>>(yr, Wt, xn, nullptr, rr, nullptr, nullptr, 0.f, 0);
        // c_new = shrink(y + MU * D^T r); momentum
        const int last = (it == 4);
        mconv<C1, C2, 1><<<grid_f, blk, SMEM_F>>>(rr, Wf, y, cp, y, last ? out : cp, yr,
                                                  mv[it], last);
    }
}

// round 9
// speedup vs baseline: 1.9463x; 1.9463x over previous
#include <cuda_runtime.h>
#include <cuda_fp16.h>
#include <cstdint>
#include <math.h>

#define HH 56
#define WW 56
#define NB 16
#define C1 64
#define C2 128
#define MU_C 0.1f
#define THR_C 0.01f

// ---------------- device scratch (allocation-free) ----------------
// fragment-ordered fp16 weights: [kt = kh*9+tap][co_blk][kblk(2)][lane(32)][reg(2)][half(2)]
__device__ __half g_Wf[2 * 9 * (C2 / 8) * 256];   // 73728 halves
__device__ __half g_Wt[4 * 9 * (C1 / 8) * 256];   // 73728 halves
__device__ float  g_xn[NB * HH * WW * C1];        // x NHWC fp32 (residual aux)
__device__ __half g_xr[NB * HH * WW * C1];        // x NHWC fp16 (conv input)
__device__ float  g_y [NB * HH * WW * C2];        // y fp32 (FISTA aux)
__device__ __half g_yr[NB * HH * WW * C2];        // y fp16 (tconv input)
__device__ float  g_cp[NB * HH * WW * C2];        // c_prev fp32
__device__ __half g_rr[NB * HH * WW * C1];        // residual fp16 (conv input)

__device__ __forceinline__ void mma_f16(float* d, const uint32_t* a, const uint32_t* b) {
    asm volatile(
        "mma.sync.aligned.m16n8k16.row.col.f32.f16.f16.f32 "
        "{%0,%1,%2,%3}, {%4,%5,%6,%7}, {%8,%9}, {%0,%1,%2,%3};"
        : "+f"(d[0]), "+f"(d[1]), "+f"(d[2]), "+f"(d[3])
        : "r"(a[0]), "r"(a[1]), "r"(a[2]), "r"(a[3]), "r"(b[0]), "r"(b[1]));
}

__device__ __forceinline__ uint32_t smem_u32(const void* p) {
    uint32_t a;
    asm("{ .reg .u64 t; cvta.to.shared.u64 t, %1; cvt.u32.u64 %0, t; }"
        : "=r"(a) : "l"(p));
    return a;
}
__device__ __forceinline__ void cp16(uint32_t dst, const void* src, int sz) {
    asm volatile("cp.async.cg.shared.global [%0], [%1], 16, %2;"
                 :: "r"(dst), "l"(src), "r"(sz));
}
__device__ __forceinline__ void cp_commit_wait() {
    asm volatile("cp.async.commit_group;");
    asm volatile("cp.async.wait_all;" ::: "memory");
}

// ---------------- prep kernels ----------------
__global__ void nchw2nhwc_kernel(const float* __restrict__ src,
                                 float* __restrict__ dfull, __half* __restrict__ rnd) {
    int i = blockIdx.x * 256 + threadIdx.x;
    int total = NB * HH * WW * C1;
    if (i >= total) return;
    int c = i & 63;
    int p = i >> 6;
    int w = p % WW;
    int q = p / WW;
    int h = q % HH;
    int n = q / HH;
    float v = src[((n * C1 + c) * HH + h) * WW + w];
    dfull[i] = v;
    rnd[i] = __float2half_rn(v);
}

__global__ void prep_w_kernel(const float* __restrict__ W) {
    const int co = blockIdx.x;
    const int tid = threadIdx.x;
    __shared__ float red[256];
    float s = 0.f;
    for (int i = tid; i < 576; i += 256) {
        float v = W[co * 576 + i];
        s += v * v;
    }
    red[tid] = s;
    __syncthreads();
    for (int off = 128; off > 0; off >>= 1) {
        if (tid < off) red[tid] += red[tid + off];
        __syncthreads();
    }
    const float inv = rsqrtf(red[0] + 1e-12f);
    for (int i = tid; i < 576; i += 256) {
        int ci = i / 9, tap = i - ci * 9;
        __half v = __float2half_rn(W[co * 576 + i] * inv);
        {   // forward: n = co, k = ci
            int k    = ci & 15;
            int lane = (co & 7) * 4 + ((k & 7) >> 1);
            int reg  = (k >> 3) & 1;
            int hp   = k & 1;
            int idx  = ((((ci >> 5) * 9 + tap) * (C2 / 8) + (co >> 3)) * 2 +
                        ((ci >> 4) & 1)) * 128 + lane * 4 + reg * 2 + hp;
            g_Wf[idx] = v;
        }
        {   // transpose: n = ci, k = co, flipped tap
            int k    = co & 15;
            int lane = (ci & 7) * 4 + ((k & 7) >> 1);
            int reg  = (k >> 3) & 1;
            int hp   = k & 1;
            int idx  = ((((co >> 5) * 9 + (8 - tap)) * (C1 / 8) + (ci >> 3)) * 2 +
                        ((co >> 4) & 1)) * 128 + lane * 4 + reg * 2 + hp;
            g_Wt[idx] = v;
        }
    }
}

// ---------------- fp16 mma.sync implicit-GEMM conv, fully resident ----------------
// D[m=128 px (2 rows x 64 cols)][n=64 cout], K = 9 taps x CIN ci (fp16 k16 MMAs).
// A: 256 halo rows x CIN halves, XOR(row&7) 16B-unit swizzle.  B: fragment order.
// Everything staged once via cp.async; zero mid-kernel syncs.
// MODE 0: first fwd;  MODE 1: FISTA fwd;  MODE 2: transpose conv + residual
template <int CIN, int COUT, int MODE>
__global__ __launch_bounds__(256, 2)
void mconv(const __half* __restrict__ in, const __half* __restrict__ wgt,
           const float* __restrict__ aux0, const float* __restrict__ aux1,
           float* __restrict__ out0, float* __restrict__ out1,
           __half* __restrict__ out2, float mcoef, int last)
{
    extern __shared__ char smem[];
    constexpr int STR    = CIN * 2;           // bytes per A row
    constexpr int UPR    = CIN / 8;           // 16B units per A row
    constexpr int KH     = CIN / 32;          // 32-ci super-stages
    constexpr int BUNITS = KH * 9 * 8 * 32;   // B 16B units
    char* sAc = smem;
    char* sBc = smem + 256 * STR;
    const uint32_t sAu = smem_u32(smem);
    const uint32_t sBu = sAu + 256 * STR;

    const int tid  = threadIdx.x;
    const int lane = tid & 31;
    const int w    = tid >> 5;
    const int wm   = w & 3;
    const int wn   = w >> 2;
    const int g    = lane >> 2;
    const int t    = lane & 3;

    const int n   = blockIdx.z;
    const int h0  = blockIdx.y * 2;
    const int co0 = blockIdx.x * 64;
    const int cb0 = co0 >> 3;

    // ---- stage A (entire CIN), zero-fill halo
    for (int i = tid; i < 256 * UPR; i += 256) {
        int row = i / UPR;
        int u   = i - row * UPR;
        int rr = row >> 6, cc = row & 63;
        int gh = h0 + rr - 1, gc = cc - 1;
        bool ok = ((unsigned)gh < (unsigned)HH) && ((unsigned)gc < (unsigned)WW);
        const __half* src = in +
            (size_t)((n * HH + (ok ? gh : 0)) * WW + (ok ? gc : 0)) * CIN + u * 8;
        cp16(sAu + row * STR + (((uint32_t)(u ^ (row & 7))) << 4), src, ok ? 16 : 0);
    }
    // ---- stage B (all kh stages), fragment order
    for (int i = tid; i < BUNITS; i += 256) {
        int chunk = i >> 5;          // (kt, nbl) 512B blocks
        int unit  = i & 31;
        int kt  = chunk >> 3;
        int nbl = chunk & 7;
        const __half* src = wgt + (size_t)(kt * (COUT / 8) + cb0 + nbl) * 256 + unit * 8;
        cp16(sBu + chunk * 512 + unit * 16, src, 16);
    }
    cp_commit_wait();
    __syncthreads();

    float acc[2][4][4];
#pragma unroll
    for (int c = 0; c < 2; c++)
#pragma unroll
        for (int nb = 0; nb < 4; nb++)
#pragma unroll
            for (int j = 0; j < 4; j++) acc[c][nb][j] = 0.f;

    for (int kh = 0; kh < KH; kh++) {
#pragma unroll 3
        for (int tap = 0; tap < 9; tap++) {
            const int kt = kh * 9 + tap;
            const int tapoff = (tap / 3) * 64 + (tap % 3);
            const int mbA = wm * 32 + g + tapoff;
#pragma unroll
            for (int kblk = 0; kblk < 2; kblk++) {
                const int ub = kh * 4 + kblk * 2;          // 16B unit of k0
                uint32_t a[2][4];
#pragma unroll
                for (int c = 0; c < 2; c++) {
                    int mb0 = mbA + c * 16;
                    int mb1 = mb0 + 8;
                    uint32_t p0 = mb0 * STR, p1 = mb1 * STR;
                    uint32_t x0 = (mb0 & 7), x1 = (mb1 & 7);
                    a[c][0] = *(const uint32_t*)(sAc + p0 + (((ub)     ^ x0) << 4) + t * 4);
                    a[c][1] = *(const uint32_t*)(sAc + p1 + (((ub)     ^ x1) << 4) + t * 4);
                    a[c][2] = *(const uint32_t*)(sAc + p0 + (((ub + 1) ^ x0) << 4) + t * 4);
                    a[c][3] = *(const uint32_t*)(sAc + p1 + (((ub + 1) ^ x1) << 4) + t * 4);
                }
#pragma unroll
                for (int nb = 0; nb < 4; nb++) {
                    uint2 bv = *(const uint2*)(sBc +
                        (size_t)(((kt * 8 + wn * 4 + nb) * 2 + kblk) * 256) + lane * 8);
                    uint32_t b[2] = { bv.x, bv.y };
                    mma_f16(acc[0][nb], a[0], b);
                    mma_f16(acc[1][nb], a[1], b);
                }
            }
        }
    }

    // ---- epilogue: fused FISTA ops
#pragma unroll
    for (int c = 0; c < 2; c++) {
#pragma unroll
        for (int half = 0; half < 2; half++) {
            int m = wm * 32 + c * 16 + g + half * 8;
            int rr = m >> 6, cc = m & 63;
            if (cc >= WW) continue;
            int h = h0 + rr;
            size_t pxb = (size_t)((n * HH + h) * WW + cc) * COUT + co0;
#pragma unroll
            for (int nb = 0; nb < 4; nb++) {
                int col = wn * 32 + nb * 8 + 2 * t;
                size_t o = pxb + col;
                float v0 = acc[c][nb][half * 2 + 0];
                float v1 = acc[c][nb][half * 2 + 1];
                if (MODE == 0) {
                    float2 r2;
                    r2.x = fmaxf(MU_C * v0 - THR_C, 0.f);
                    r2.y = fmaxf(MU_C * v1 - THR_C, 0.f);
                    *(float2*)(out0 + o) = r2;                       // y fp32
                    *(float2*)(out1 + o) = r2;                       // c_prev
                    *(half2*)(out2 + o) = __floats2half2_rn(r2.x, r2.y);  // y fp16
                } else if (MODE == 1) {
                    float2 yv = *(const float2*)(aux0 + o);
                    float cn0 = fmaxf(yv.x + MU_C * v0 - THR_C, 0.f);
                    float cn1 = fmaxf(yv.y + MU_C * v1 - THR_C, 0.f);
                    if (last) {
                        out1[((size_t)(n * C2 + co0 + col) * HH + h) * WW + cc] = cn0;
                        out1[((size_t)(n * C2 + co0 + col + 1) * HH + h) * WW + cc] = cn1;
                    } else {
                        float2 cpv = *(const float2*)(aux1 + o);
                        float2 c2; c2.x = cn0; c2.y = cn1;
                        *(float2*)(out1 + o) = c2;                   // c_prev
                        float2 y2;
                        y2.x = cn0 + mcoef * (cn0 - cpv.x);
                        y2.y = cn1 + mcoef * (cn1 - cpv.y);
                        *(float2*)(out0 + o) = y2;                   // y fp32
                        *(half2*)(out2 + o) = __floats2half2_rn(y2.x, y2.y);  // y fp16
                    }
                } else {
                    float2 xv = *(const float2*)(aux0 + o);
                    *(half2*)(out2 + o) = __floats2half2_rn(xv.x - v0, xv.y - v1);  // r fp16
                }
            }
        }
    }
}

// ---------------- launcher ----------------
extern "C" void kernel_launch(void* const* d_in, const int* in_sizes, int n_in,
                              void* d_out, int out_size)
{
    const float* x = (const float*)d_in[0];   // [16,64,56,56] NCHW
    const float* W = (const float*)d_in[1];   // [128,64,3,3]
    float* out = (float*)d_out;               // [16,128,56,56] NCHW

    __half *Wf, *Wt, *xr, *yr, *rr;
    float *xn, *y, *cp;
    cudaGetSymbolAddress((void**)&Wf, g_Wf);
    cudaGetSymbolAddress((void**)&Wt, g_Wt);
    cudaGetSymbolAddress((void**)&xn, g_xn);
    cudaGetSymbolAddress((void**)&xr, g_xr);
    cudaGetSymbolAddress((void**)&y,  g_y);
    cudaGetSymbolAddress((void**)&yr, g_yr);
    cudaGetSymbolAddress((void**)&cp, g_cp);
    cudaGetSymbolAddress((void**)&rr, g_rr);

    float mv[5];
    {
        double t = 1.0;
        for (int i = 0; i < 5; i++) {
            double tn = (1.0 + sqrt(1.0 + 4.0 * t * t)) / 2.0;
            mv[i] = (float)((t - 1.0) / tn);
            t = tn;
        }
    }

    const int SMEM_F = 256 * (C1 * 2) + 2 * 9 * 8 * 512;   // 32768 + 73728 = 106496
    const int SMEM_T = 256 * (C2 * 2) + 4 * 9 * 8 * 512;   // 65536 + 147456 = 212992
    cudaFuncSetAttribute(mconv<C1, C2, 0>, cudaFuncAttributeMaxDynamicSharedMemorySize, SMEM_F);
    cudaFuncSetAttribute(mconv<C1, C2, 1>, cudaFuncAttributeMaxDynamicSharedMemorySize, SMEM_F);
    cudaFuncSetAttribute(mconv<C2, C1, 2>, cudaFuncAttributeMaxDynamicSharedMemorySize, SMEM_T);
    cudaFuncSetAttribute(mconv<C1, C2, 0>, cudaFuncAttributePreferredSharedMemoryCarveout, 100);
    cudaFuncSetAttribute(mconv<C1, C2, 1>, cudaFuncAttributePreferredSharedMemoryCarveout, 100);
    cudaFuncSetAttribute(mconv<C2, C1, 2>, cudaFuncAttributePreferredSharedMemoryCarveout, 100);

    int total = NB * HH * WW * C1;
    nchw2nhwc_kernel<<<(total + 255) / 256, 256>>>(x, xn, xr);
    prep_w_kernel<<<128, 256>>>(W);

    dim3 blk(256, 1, 1);
    dim3 grid_f(C2 / 64, HH / 2, NB);   // (2, 28, 16)
    dim3 grid_t(C1 / 64, HH / 2, NB);   // (1, 28, 16)

    // iteration 0: c = shrink(MU * D^T x); y = c; cp = c
    mconv<C1, C2, 0><<<grid_f, blk, SMEM_F>>>(xr, Wf, nullptr, nullptr, y, cp, yr, 0.f, 0);

    for (int it = 0; it < 5; it++) {
        // r = x - D y  (transpose conv + residual, fp16 for next conv)
        mconv<C2, C1, 2><<<grid_t, blk, SMEM_T>>>(yr, Wt, xn, nullptr, nullptr, nullptr, rr, 0.f, 0);
        // c_new = shrink(y + MU * D^T r); momentum
        const int last = (it == 4);
        mconv<C1, C2, 1><<<grid_f, blk, SMEM_F>>>(rr, Wf, y, cp, y, last ? out : cp, yr,
                                                  mv[it], last);
    }
}

// round 11
// speedup vs baseline: 2.0238x; 1.0398x over previous
#include <cuda_runtime.h>
#include <cuda_fp16.h>
#include <cstdint>
#include <math.h>

#define HH 56
#define WW 56
#define NB 16
#define C1 64
#define C2 128
#define MU_C 0.1f
#define THR_C 0.01f

// ---------------- device scratch (allocation-free) ----------------
// fragment-ordered fp16 weights: [kt][co_blk][lane(32)][kblk(2)][reg(2)][half(2)]
__device__ __half g_Wf[2 * 9 * (C2 / 8) * 256];   // 73728 halves
__device__ __half g_Wt[4 * 9 * (C1 / 8) * 256];   // 73728 halves
__device__ float  g_xn[NB * HH * WW * C1];        // x NHWC fp32 (residual aux)
__device__ __half g_xr[NB * HH * WW * C1];        // x NHWC fp16 (conv input)
__device__ float  g_y [NB * HH * WW * C2];        // y fp32 (FISTA aux)
__device__ __half g_yr[NB * HH * WW * C2];        // y fp16 (tconv input)
__device__ float  g_cp[NB * HH * WW * C2];        // c_prev fp32
__device__ __half g_rr[NB * HH * WW * C1];        // residual fp16 (conv input)

__device__ __forceinline__ void mma_f16(float* d, const uint32_t* a,
                                        uint32_t b0, uint32_t b1) {
    asm volatile(
        "mma.sync.aligned.m16n8k16.row.col.f32.f16.f16.f32 "
        "{%0,%1,%2,%3}, {%4,%5,%6,%7}, {%8,%9}, {%0,%1,%2,%3};"
        : "+f"(d[0]), "+f"(d[1]), "+f"(d[2]), "+f"(d[3])
        : "r"(a[0]), "r"(a[1]), "r"(a[2]), "r"(a[3]), "r"(b0), "r"(b1));
}

__device__ __forceinline__ void ldsm_x4(uint32_t* r, uint32_t addr) {
    asm volatile("ldmatrix.sync.aligned.m8n8.x4.shared.b16 {%0,%1,%2,%3}, [%4];"
                 : "=r"(r[0]), "=r"(r[1]), "=r"(r[2]), "=r"(r[3]) : "r"(addr));
}

__device__ __forceinline__ uint32_t smem_u32(const void* p) {
    uint32_t a;
    asm("{ .reg .u64 t; cvta.to.shared.u64 t, %1; cvt.u32.u64 %0, t; }"
        : "=r"(a) : "l"(p));
    return a;
}
__device__ __forceinline__ void cp16(uint32_t dst, const void* src, int sz) {
    asm volatile("cp.async.cg.shared.global [%0], [%1], 16, %2;"
                 :: "r"(dst), "l"(src), "r"(sz));
}
__device__ __forceinline__ void cp_commit_wait() {
    asm volatile("cp.async.commit_group;");
    asm volatile("cp.async.wait_all;" ::: "memory");
}

// ---------------- prep kernels ----------------
__global__ void nchw2nhwc_kernel(const float* __restrict__ src,
                                 float* __restrict__ dfull, __half* __restrict__ rnd) {
    int i = blockIdx.x * 256 + threadIdx.x;
    int total = NB * HH * WW * C1;
    if (i >= total) return;
    int c = i & 63;
    int p = i >> 6;
    int w = p % WW;
    int q = p / WW;
    int h = q % HH;
    int n = q / HH;
    float v = src[((n * C1 + c) * HH + h) * WW + w];
    dfull[i] = v;
    rnd[i] = __float2half_rn(v);
}

__global__ void prep_w_kernel(const float* __restrict__ W) {
    const int co = blockIdx.x;
    const int tid = threadIdx.x;
    __shared__ float red[256];
    float s = 0.f;
    for (int i = tid; i < 576; i += 256) {
        float v = W[co * 576 + i];
        s += v * v;
    }
    red[tid] = s;
    __syncthreads();
    for (int off = 128; off > 0; off >>= 1) {
        if (tid < off) red[tid] += red[tid + off];
        __syncthreads();
    }
    const float inv = rsqrtf(red[0] + 1e-12f);
    for (int i = tid; i < 576; i += 256) {
        int ci = i / 9, tap = i - ci * 9;
        __half v = __float2half_rn(W[co * 576 + i] * inv);
        {   // forward: n = co, k = ci
            int k    = ci & 15;
            int kblk = (ci >> 4) & 1;
            int lane = (co & 7) * 4 + ((k & 7) >> 1);
            int reg  = (k >> 3) & 1;
            int hp   = k & 1;
            int idx  = (((ci >> 5) * 9 + tap) * (C2 / 8) + (co >> 3)) * 256 +
                       lane * 8 + kblk * 4 + reg * 2 + hp;
            g_Wf[idx] = v;
        }
        {   // transpose: n = ci, k = co, flipped tap
            int k    = co & 15;
            int kblk = (co >> 4) & 1;
            int lane = (ci & 7) * 4 + ((k & 7) >> 1);
            int reg  = (k >> 3) & 1;
            int hp   = k & 1;
            int idx  = (((co >> 5) * 9 + (8 - tap)) * (C1 / 8) + (ci >> 3)) * 256 +
                       lane * 8 + kblk * 4 + reg * 2 + hp;
            g_Wt[idx] = v;
        }
    }
}

// ---------------- fp16 mma.sync implicit-GEMM conv (LDSM + LDS.128 B) ------
// D[m=128 px (2 rows x 64 cols)][n=64 cout], K = 9 taps x CIN ci.
// A: 256 halo rows x CIN halves, XOR(row&7) 16B-unit swizzle, LDSM.x4 reads.
// B: fragment order [kt][cb][lane][kblk][reg]; fwd fully resident,
//    tconv restaged per 32-ci stage (keeps CTA smem <= 102.4 KB -> 2 CTA/SM).
// MODE 0: first fwd;  MODE 1: FISTA fwd;  MODE 2: transpose conv + residual
template <int CIN, int COUT, int MODE>
__global__ __launch_bounds__(256, 2)
void mconv(const __half* __restrict__ in, const __half* __restrict__ wgt,
           const float* __restrict__ aux0, const float* __restrict__ aux1,
           float* __restrict__ out0, float* __restrict__ out1,
           __half* __restrict__ out2, float mcoef, int last)
{
    extern __shared__ char smem[];
    constexpr int STR    = CIN * 2;           // bytes per A row
    constexpr int UPR    = CIN / 8;           // 16B units per A row
    constexpr int KH     = CIN / 32;          // 32-ci super-stages
    constexpr bool BRES  = (CIN == 64);       // all B resident?
    constexpr int BUNITS = 9 * 8 * 32;        // B 16B units per kh stage
    char* sBc = smem + 256 * STR;
    const uint32_t sAu = smem_u32(smem);
    const uint32_t sBu = sAu + 256 * STR;

    const int tid  = threadIdx.x;
    const int lane = tid & 31;
    const int w    = tid >> 5;
    const int wm   = w & 3;
    const int wn   = w >> 2;
    const int g    = lane >> 2;
    const int t    = lane & 3;

    const int n   = blockIdx.z;
    const int h0  = blockIdx.y * 2;
    const int co0 = blockIdx.x * 64;
    const int cb0 = co0 >> 3;

    // per-lane LDSM row bases (c = 0 / 1 m-halves)
    const int rb0 = wm * 32 + (lane & 7) + (lane & 8);
    const int rb1 = rb0 + 16;
    const int ulane = lane >> 4;              // +unit for matrices 2,3

    // ---- stage A (entire CIN), zero-fill halo
    for (int i = tid; i < 256 * UPR; i += 256) {
        int row = i / UPR;
        int u   = i - row * UPR;
        int rr = row >> 6, cc = row & 63;
        int gh = h0 + rr - 1, gc = cc - 1;
        bool ok = ((unsigned)gh < (unsigned)HH) && ((unsigned)gc < (unsigned)WW);
        const __half* src = in +
            (size_t)((n * HH + (ok ? gh : 0)) * WW + (ok ? gc : 0)) * CIN + u * 8;
        cp16(sAu + row * STR + (((uint32_t)(u ^ (row & 7))) << 4), src, ok ? 16 : 0);
    }
    // ---- stage B: fwd -> all kt now; tconv -> kh = 0 now
    {
        const int nun = BRES ? KH * BUNITS : BUNITS;
        for (int i = tid; i < nun; i += 256) {
            int chunk = i >> 5;
            int unit  = i & 31;
            int kt  = chunk >> 3;
            int nbl = chunk & 7;
            const __half* src = wgt + (size_t)(kt * (COUT / 8) + cb0 + nbl) * 256 + unit * 8;
            cp16(sBu + chunk * 512 + unit * 16, src, 16);
        }
    }
    cp_commit_wait();
    __syncthreads();

    float acc[2][4][4];
#pragma unroll
    for (int c = 0; c < 2; c++)
#pragma unroll
        for (int nb = 0; nb < 4; nb++)
#pragma unroll
            for (int j = 0; j < 4; j++) acc[c][nb][j] = 0.f;

    for (int kh = 0; kh < KH; kh++) {
        if (!BRES && kh > 0) {
            __syncthreads();
            for (int i = tid; i < BUNITS; i += 256) {
                int chunk = i >> 5;
                int unit  = i & 31;
                int tap = chunk >> 3;
                int nbl = chunk & 7;
                const __half* src = wgt +
                    (size_t)((kh * 9 + tap) * (COUT / 8) + cb0 + nbl) * 256 + unit * 8;
                cp16(sBu + chunk * 512 + unit * 16, src, 16);
            }
            cp_commit_wait();
            __syncthreads();
        }

#pragma unroll 3
        for (int tap = 0; tap < 9; tap++) {
            const int ktL = (BRES ? kh * 9 + tap : tap);     // local B block
            const int tapoff = (tap / 3) * 64 + (tap % 3);
            const int r0 = rb0 + tapoff;
            const int r1 = rb1 + tapoff;
            uint32_t a[2][2][4];
#pragma unroll
            for (int kblk = 0; kblk < 2; kblk++) {
                const int u = kh * 4 + kblk * 2 + ulane;
                ldsm_x4(a[0][kblk], sAu + r0 * STR + (((uint32_t)(u ^ (r0 & 7))) << 4));
                ldsm_x4(a[1][kblk], sAu + r1 * STR + (((uint32_t)(u ^ (r1 & 7))) << 4));
            }
#pragma unroll
            for (int nb = 0; nb < 4; nb++) {
                uint4 bv = *(const uint4*)(sBc +
                    (size_t)((ktL * 8 + wn * 4 + nb) * 512) + lane * 16);
                mma_f16(acc[0][nb], a[0][0], bv.x, bv.y);
                mma_f16(acc[1][nb], a[1][0], bv.x, bv.y);
                mma_f16(acc[0][nb], a[0][1], bv.z, bv.w);
                mma_f16(acc[1][nb], a[1][1], bv.z, bv.w);
            }
        }
    }

    // ---- epilogue: fused FISTA ops
#pragma unroll
    for (int c = 0; c < 2; c++) {
#pragma unroll
        for (int half = 0; half < 2; half++) {
            int m = wm * 32 + c * 16 + g + half * 8;
            int rr = m >> 6, cc = m & 63;
            if (cc >= WW) continue;
            int h = h0 + rr;
            size_t pxb = (size_t)((n * HH + h) * WW + cc) * COUT + co0;
#pragma unroll
            for (int nb = 0; nb < 4; nb++) {
                int col = wn * 32 + nb * 8 + 2 * t;
                size_t o = pxb + col;
                float v0 = acc[c][nb][half * 2 + 0];
                float v1 = acc[c][nb][half * 2 + 1];
                if (MODE == 0) {
                    float2 r2;
                    r2.x = fmaxf(MU_C * v0 - THR_C, 0.f);
                    r2.y = fmaxf(MU_C * v1 - THR_C, 0.f);
                    *(float2*)(out0 + o) = r2;                       // y fp32
                    *(float2*)(out1 + o) = r2;                       // c_prev
                    *(half2*)(out2 + o) = __floats2half2_rn(r2.x, r2.y);  // y fp16
                } else if (MODE == 1) {
                    float2 yv = *(const float2*)(aux0 + o);
                    float cn0 = fmaxf(yv.x + MU_C * v0 - THR_C, 0.f);
                    float cn1 = fmaxf(yv.y + MU_C * v1 - THR_C, 0.f);
                    if (last) {
                        out1[((size_t)(n * C2 + co0 + col) * HH + h) * WW + cc] = cn0;
                        out1[((size_t)(n * C2 + co0 + col + 1) * HH + h) * WW + cc] = cn1;
                    } else {
                        float2 cpv = *(const float2*)(aux1 + o);
                        float2 c2; c2.x = cn0; c2.y = cn1;
                        *(float2*)(out1 + o) = c2;                   // c_prev
                        float2 y2;
                        y2.x = cn0 + mcoef * (cn0 - cpv.x);
                        y2.y = cn1 + mcoef * (cn1 - cpv.y);
                        *(float2*)(out0 + o) = y2;                   // y fp32
                        *(half2*)(out2 + o) = __floats2half2_rn(y2.x, y2.y);  // y fp16
                    }
                } else {
                    float2 xv = *(const float2*)(aux0 + o);
                    *(half2*)(out2 + o) = __floats2half2_rn(xv.x - v0, xv.y - v1);  // r fp16
                }
            }
        }
    }
}

// ---------------- launcher ----------------
extern "C" void kernel_launch(void* const* d_in, const int* in_sizes, int n_in,
                              void* d_out, int out_size)
{
    const float* x = (const float*)d_in[0];   // [16,64,56,56] NCHW
    const float* W = (const float*)d_in[1];   // [128,64,3,3]
    float* out = (float*)d_out;               // [16,128,56,56] NCHW

    __half *Wf, *Wt, *xr, *yr, *rr;
    float *xn, *y, *cp;
    cudaGetSymbolAddress((void**)&Wf, g_Wf);
    cudaGetSymbolAddress((void**)&Wt, g_Wt);
    cudaGetSymbolAddress((void**)&xn, g_xn);
    cudaGetSymbolAddress((void**)&xr, g_xr);
    cudaGetSymbolAddress((void**)&y,  g_y);
    cudaGetSymbolAddress((void**)&yr, g_yr);
    cudaGetSymbolAddress((void**)&cp, g_cp);
    cudaGetSymbolAddress((void**)&rr, g_rr);

    float mv[5];
    {
        double t = 1.0;
        for (int i = 0; i < 5; i++) {
            double tn = (1.0 + sqrt(1.0 + 4.0 * t * t)) / 2.0;
            mv[i] = (float)((t - 1.0) / tn);
            t = tn;
        }
    }

    const int SMEM_F = 256 * (C1 * 2) + 2 * 9 * 8 * 512;   // 106496 (2 CTA/SM)
    const int SMEM_T = 256 * (C2 * 2) + 9 * 8 * 512;       // 102400 (2 CTA/SM)
    cudaFuncSetAttribute(mconv<C1, C2, 0>, cudaFuncAttributeMaxDynamicSharedMemorySize, SMEM_F);
    cudaFuncSetAttribute(mconv<C1, C2, 1>, cudaFuncAttributeMaxDynamicSharedMemorySize, SMEM_F);
    cudaFuncSetAttribute(mconv<C2, C1, 2>, cudaFuncAttributeMaxDynamicSharedMemorySize, SMEM_T);
    cudaFuncSetAttribute(mconv<C1, C2, 0>, cudaFuncAttributePreferredSharedMemoryCarveout, 100);
    cudaFuncSetAttribute(mconv<C1, C2, 1>, cudaFuncAttributePreferredSharedMemoryCarveout, 100);
    cudaFuncSetAttribute(mconv<C2, C1, 2>, cudaFuncAttributePreferredSharedMemoryCarveout, 100);

    int total = NB * HH * WW * C1;
    nchw2nhwc_kernel<<<(total + 255) / 256, 256>>>(x, xn, xr);
    prep_w_kernel<<<128, 256>>>(W);

    dim3 blk(256, 1, 1);
    dim3 grid_f(C2 / 64, HH / 2, NB);   // (2, 28, 16)
    dim3 grid_t(C1 / 64, HH / 2, NB);   // (1, 28, 16)

    // iteration 0: c = shrink(MU * D^T x); y = c; cp = c
    mconv<C1, C2, 0><<<grid_f, blk, SMEM_F>>>(xr, Wf, nullptr, nullptr, y, cp, yr, 0.f, 0);

    for (int it = 0; it < 5; it++) {
        // r = x - D y  (transpose conv + residual, fp16 for next conv)
        mconv<C2, C1, 2><<<grid_t, blk, SMEM_T>>>(yr, Wt, xn, nullptr, nullptr, nullptr, rr, 0.f, 0);
        // c_new = shrink(y + MU * D^T r); momentum
        const int last = (it == 4);
        mconv<C1, C2, 1><<<grid_f, blk, SMEM_F>>>(rr, Wf, y, cp, y, last ? out : cp, yr,
                                                  mv[it], last);
    }
}